// round 11
// baseline (speedup 1.0000x reference)
#include <cuda_runtime.h>
#include <cstdint>
#include <math.h>

// Problem constants
#define PS   2048
#define PD   64
#define PBH  32
#define TQ   64
#define TK   64
#define NQB  (PS / TQ)     // 32
#define NTH  128

#define OUT_ELEMS   (PBH * PS * PD)
#define PATTN_ELEMS ((size_t)PBH * (size_t)PS * (size_t)PS)

// 129-row sin/cos table (causal => clipped rel index in [0,128])
__device__ float g_table[129 * 64];
// K transposed per head: [bh][d][s]
__device__ float g_KT[(size_t)PBH * PD * PS];
// Q transposed per head (prescaled 1/8): [bh][d][s]
__device__ float g_QT[(size_t)PBH * PD * PS];
// bias table: g_QR[bh][s][j], j in [0,128], row stride 132
__device__ float g_QR[(size_t)PBH * PS * 132];

// ---------------- f32x2 packed-FMA helpers ----------------
__device__ __forceinline__ unsigned long long pk2(float a, float b) {
    unsigned long long r;
    asm("mov.b64 %0,{%1,%2};" : "=l"(r) : "f"(a), "f"(b));
    return r;
}
__device__ __forceinline__ float2 up2(unsigned long long v) {
    float2 r;
    asm("mov.b64 {%0,%1},%2;" : "=f"(r.x), "=f"(r.y) : "l"(v));
    return r;
}
#define FMA2(d, a, b) asm("fma.rn.f32x2 %0,%1,%2,%0;" : "+l"(d) : "l"(a), "l"(b))

__device__ __forceinline__ unsigned smem_u32(const void* p) {
    return (unsigned)__cvta_generic_to_shared(p);
}
__device__ __forceinline__ void cpa16(unsigned s, const void* g) {
    asm volatile("cp.async.cg.shared.global [%0], [%1], 16;" :: "r"(s), "l"(g));
}

__global__ void init_table_kernel() {
    int j = blockIdx.x;     // 0..128
    int d = threadIdx.x;    // 0..63
    int i2 = d & ~1;
    float div = expf((float)i2 * (-logf(10000.0f) / 64.0f));
    float ang = (float)j * div;
    g_table[j * 64 + d] = (d & 1) ? cosf(ang) : sinf(ang);
}

// One-time transpose: z=0: K -> g_KT ; z=1: Q*0.125 -> g_QT
__global__ void __launch_bounds__(256, 4)
transpose_qk_kernel(const float* __restrict__ K, const float* __restrict__ Q) {
    __shared__ float t[64 * 68];
    const int tid = threadIdx.x;
    const int st  = blockIdx.x;
    const int bh  = blockIdx.y;
    const bool isQ = (blockIdx.z != 0);
    const float* src = isQ ? Q : K;
    float* dst = isQ ? g_QT : g_KT;
    const float scale = isQ ? 0.125f : 1.0f;
    const float4* Sb = (const float4*)(src + ((size_t)bh * PS + st * 64) * PD);
    #pragma unroll
    for (int i = 0; i < 4; i++) {
        int idx = tid + i * 256;
        int row = idx >> 4, d4 = idx & 15;
        float4 v = Sb[idx];
        v.x *= scale; v.y *= scale; v.z *= scale; v.w *= scale;
        ((float4*)(t + row * 68))[d4] = v;
    }
    __syncthreads();
    #pragma unroll
    for (int i = 0; i < 4; i++) {
        int idx = tid + i * 256;
        int d = idx >> 4, s4 = idx & 15;
        float4 v;
        v.x = t[(4 * s4 + 0) * 68 + d];
        v.y = t[(4 * s4 + 1) * 68 + d];
        v.z = t[(4 * s4 + 2) * 68 + d];
        v.w = t[(4 * s4 + 3) * 68 + d];
        *(float4*)(dst + ((size_t)bh * PD + d) * PS + st * 64 + 4 * s4) = v;
    }
}

// bias pre-kernel: g_QR[bh][s][j] = (Q[bh][s]/8) . T[j]
__global__ void __launch_bounds__(256, 4)
bias_kernel(const float* __restrict__ Q) {
    __shared__ float qs[64 * 68];
    __shared__ float tb[129 * 68];
    const int tid = threadIdx.x;
    const int st  = blockIdx.x;
    const int bh  = blockIdx.y;
    {
        const float4* Qb = (const float4*)(Q + ((size_t)bh * PS + st * 64) * PD);
        #pragma unroll
        for (int i = 0; i < 4; i++) {
            int idx = tid + i * 256;
            int row = idx >> 4, d4 = idx & 15;
            float4 v = Qb[idx];
            v.x *= 0.125f; v.y *= 0.125f; v.z *= 0.125f; v.w *= 0.125f;
            ((float4*)(qs + row * 68))[d4] = v;
        }
        for (int idx = tid; idx < 129 * 16; idx += 256) {
            int row = idx >> 4, d4 = idx & 15;
            ((float4*)(tb + row * 68))[d4] = ((const float4*)g_table)[idx];
        }
    }
    __syncthreads();
    float* dst = g_QR + ((size_t)bh * PS + st * 64) * 132;
    for (int t = tid; t < 64 * 129; t += 256) {
        int r = t / 129;
        int j = t - r * 129;
        const float4* qa = (const float4*)(qs + r * 68);
        const float4* ta = (const float4*)(tb + j * 68);
        float acc = 0.0f;
        #pragma unroll
        for (int d4 = 0; d4 < 16; d4++) {
            float4 a = qa[d4], b = ta[d4];
            acc += a.x * b.x + a.y * b.y + a.z * b.z + a.w * b.w;
        }
        dst[r * 132 + j] = acc;
    }
}

// ---------------- smem layout (floats), total 12352 = 49,408 B ----------------
#define OFF_QT 0        // [64][64]  Q^T tile (prescaled), d-major
#define OFF_KT 4096     // [64][64]  K^T tile; REUSED as PT (e^T, slot-swizzled)
#define OFF_VS 8192     // [64][64]  V tile natural
#define OFF_LR 12288    // [64]      1/l
#define SM_TOT 12352
// epilogue band overlay: [64][132] at sm+0 (8448 floats <= 12288)

__global__ void __launch_bounds__(NTH, 4)
attn_relpos_kernel(const float* __restrict__ V,
                   float* __restrict__ out,
                   float* __restrict__ P)
{
    extern __shared__ float sm[];
    float* QT = sm + OFF_QT;
    float* KT = sm + OFF_KT;   // also PT after QK GEMM
    float* VS = sm + OFF_VS;
    float* LR = sm + OFF_LR;

    const int tid = threadIdx.x;
    const int bh  = blockIdx.x;
    const int qt  = (NQB - 1) - blockIdx.y;   // heavy tiles first
    const int q0  = qt * TQ;
    const int tx  = tid & 7;        // 8 col-groups (8 cols each)
    const int ty  = tid >> 3;       // 16 row-groups (4 rows each)
    const int tx8 = tx * 8;
    const int ty4 = ty * 4;
    const int nkt = qt + 1;

    const unsigned qtA = smem_u32(QT);
    const unsigned ktA = smem_u32(KT);
    const unsigned vsA = smem_u32(VS);
    const float* KTg0 = g_KT + (size_t)bh * PD * PS;
    const float* QTg0 = g_QT + (size_t)bh * PD * PS;
    const float* Vg0  = V + (size_t)bh * PS * PD;

    // ---------- async-load Q^T tile (group) ----------
    #pragma unroll
    for (int i = 0; i < 8; i++) {
        int idx = tid + i * NTH;           // 0..1023
        int d = idx >> 4, c4 = idx & 15;
        cpa16(qtA + (d * 64 + c4 * 4) * 4, QTg0 + (size_t)d * PS + q0 + c4 * 4);
    }
    asm volatile("cp.async.commit_group;");

    // per-row far-tile factor + bias row pointers (L2-resident)
    const float* qrRow[4];
    float rf[4];
    #pragma unroll
    for (int rr = 0; rr < 4; rr++) {
        qrRow[rr] = g_QR + ((size_t)bh * PS + q0 + ty4 + rr) * 132;
        rf[rr] = __expf(qrRow[rr][0]);
    }

    unsigned long long O2[4][4];   // [row][dcol-pair]
    #pragma unroll
    for (int rr = 0; rr < 4; rr++)
        #pragma unroll
        for (int cp = 0; cp < 4; cp++) O2[rr][cp] = 0ull;
    float lp[4] = {0.f, 0.f, 0.f, 0.f};

    const size_t rowbase = (size_t)bh * PS + q0;

    for (int kt = 0; kt < nkt; kt++) {
        __syncthreads();   // prior PV done reading PT(=KT buf) and VS
        // async-load K^T tile (group), then V tile (group)
        {
            const float* KTg = KTg0 + kt * TK;
            #pragma unroll
            for (int i = 0; i < 8; i++) {
                int idx = tid + i * NTH;
                int d = idx >> 4, c4 = idx & 15;
                cpa16(ktA + (d * 64 + c4 * 4) * 4, KTg + (size_t)d * PS + c4 * 4);
            }
            asm volatile("cp.async.commit_group;");
            const float* Vg = Vg0 + (size_t)kt * TK * PD;
            #pragma unroll
            for (int i = 0; i < 8; i++) {
                int idx = tid + i * NTH;
                int a = idx >> 4, b4 = idx & 15;
                cpa16(vsA + (a * 64 + b4 * 4) * 4, Vg + idx * 4);
            }
            asm volatile("cp.async.commit_group;");
        }
        asm volatile("cp.async.wait_group 1;");   // QT(+KT) ready; VS in flight
        __syncthreads();

        // -------- QK GEMM: acc[row][colpair], cols packed from KT --------
        unsigned long long acc[4][4];
        #pragma unroll
        for (int rr = 0; rr < 4; rr++)
            #pragma unroll
            for (int cp = 0; cp < 4; cp++) acc[rr][cp] = 0ull;

        #pragma unroll 16
        for (int d = 0; d < 64; d++) {
            float4 qv = *(const float4*)(QT + d * 64 + ty4);
            ulonglong2 k01 = *(const ulonglong2*)(KT + d * 64 + tx8);
            ulonglong2 k23 = *(const ulonglong2*)(KT + d * 64 + tx8 + 4);
            unsigned long long q0d = pk2(qv.x, qv.x), q1d = pk2(qv.y, qv.y);
            unsigned long long q2d = pk2(qv.z, qv.z), q3d = pk2(qv.w, qv.w);
            FMA2(acc[0][0], q0d, k01.x); FMA2(acc[0][1], q0d, k01.y);
            FMA2(acc[0][2], q0d, k23.x); FMA2(acc[0][3], q0d, k23.y);
            FMA2(acc[1][0], q1d, k01.x); FMA2(acc[1][1], q1d, k01.y);
            FMA2(acc[1][2], q1d, k23.x); FMA2(acc[1][3], q1d, k23.y);
            FMA2(acc[2][0], q2d, k01.x); FMA2(acc[2][1], q2d, k01.y);
            FMA2(acc[2][2], q2d, k23.x); FMA2(acc[2][3], q2d, k23.y);
            FMA2(acc[3][0], q3d, k01.x); FMA2(acc[3][1], q3d, k01.y);
            FMA2(acc[3][2], q3d, k23.x); FMA2(acc[3][3], q3d, k23.y);
        }
        __syncthreads();   // all QK reads of KT done before PT overwrite

        // -------- scores -> e --------
        float er[4][8];
        #pragma unroll
        for (int rr = 0; rr < 4; rr++)
            #pragma unroll
            for (int cp = 0; cp < 4; cp++) {
                float2 s2 = up2(acc[rr][cp]);
                er[rr][2 * cp]     = s2.x;
                er[rr][2 * cp + 1] = s2.y;
            }

        if (kt * TK + 191 <= q0) {
            #pragma unroll
            for (int rr = 0; rr < 4; rr++)
                #pragma unroll
                for (int cc = 0; cc < 8; cc++)
                    er[rr][cc] = rf[rr] * __expf(er[rr][cc]);
        } else {
            #pragma unroll
            for (int rr = 0; rr < 4; rr++) {
                int R = ty4 + rr;
                int jbase = kt * TK + tx8 - (q0 + R) + 128;
                #pragma unroll
                for (int cc = 0; cc < 8; cc++) {
                    int jr = jbase + cc;
                    float ev = 0.0f;
                    if (jr <= 128) {
                        int jc = jr < 0 ? 0 : jr;
                        ev = __expf(er[rr][cc] + qrRow[rr][jc]);
                    }
                    er[rr][cc] = ev;
                }
            }
        }
        #pragma unroll
        for (int rr = 0; rr < 4; rr++)
            lp[rr] += ((er[rr][0] + er[rr][1]) + (er[rr][2] + er[rr][3]))
                    + ((er[rr][4] + er[rr][5]) + (er[rr][6] + er[rr][7]));

        // unnormalized e -> global P (two float4 per row)
        if (P) {
            #pragma unroll
            for (int rr = 0; rr < 4; rr++) {
                float* pr = P + (rowbase + ty4 + rr) * (size_t)PS + kt * TK + tx8;
                *(float4*)pr       = make_float4(er[rr][0], er[rr][1], er[rr][2], er[rr][3]);
                *(float4*)(pr + 4) = make_float4(er[rr][4], er[rr][5], er[rr][6], er[rr][7]);
            }
        }
        // e^T into PT (=KT buffer), slot-swizzled: slot = ty ^ (c>>3) ^ (c&7)
        {
            float* PT = KT;
            #pragma unroll
            for (int cc = 0; cc < 8; cc++) {
                int c = tx8 + cc;
                int slot = ty ^ tx ^ cc;
                *(float4*)(PT + c * 64 + 4 * slot) =
                    make_float4(er[0][cc], er[1][cc], er[2][cc], er[3][cc]);
            }
        }
        asm volatile("cp.async.wait_group 0;");   // VS ready
        __syncthreads();   // PT visible to all

        // -------- PV GEMM --------
        {
            const float* PT = KT;
            for (int ca = 0; ca < 8; ca++) {
                const int sb = ty ^ ca;
                const float* PTa = PT + ca * 8 * 64;
                const float* VSa = VS + ca * 8 * 64 + tx8;
                #pragma unroll
                for (int cb = 0; cb < 8; cb++) {
                    int slot = sb ^ cb;
                    float4 e4 = *(const float4*)(PTa + cb * 64 + 4 * slot);
                    ulonglong2 v01 = *(const ulonglong2*)(VSa + cb * 64);
                    ulonglong2 v23 = *(const ulonglong2*)(VSa + cb * 64 + 4);
                    unsigned long long e0 = pk2(e4.x, e4.x), e1 = pk2(e4.y, e4.y);
                    unsigned long long e2 = pk2(e4.z, e4.z), e3 = pk2(e4.w, e4.w);
                    FMA2(O2[0][0], e0, v01.x); FMA2(O2[0][1], e0, v01.y);
                    FMA2(O2[0][2], e0, v23.x); FMA2(O2[0][3], e0, v23.y);
                    FMA2(O2[1][0], e1, v01.x); FMA2(O2[1][1], e1, v01.y);
                    FMA2(O2[1][2], e1, v23.x); FMA2(O2[1][3], e1, v23.y);
                    FMA2(O2[2][0], e2, v01.x); FMA2(O2[2][1], e2, v01.y);
                    FMA2(O2[2][2], e2, v23.x); FMA2(O2[2][3], e2, v23.y);
                    FMA2(O2[3][0], e3, v01.x); FMA2(O2[3][1], e3, v01.y);
                    FMA2(O2[3][2], e3, v23.x); FMA2(O2[3][3], e3, v23.y);
                }
            }
        }
    }

    // ---------- row sums -> 1/l (reduce across 8 tx lanes) ----------
    #pragma unroll
    for (int off = 1; off < 8; off <<= 1)
        #pragma unroll
        for (int rr = 0; rr < 4; rr++)
            lp[rr] += __shfl_xor_sync(0xffffffffu, lp[rr], off, 8);
    float linv[4];
    #pragma unroll
    for (int rr = 0; rr < 4; rr++) linv[rr] = 1.0f / lp[rr];
    if (tx == 0) {
        #pragma unroll
        for (int rr = 0; rr < 4; rr++) LR[ty4 + rr] = linv[rr];
    }
    __syncthreads();   // LR visible; all GEMM smem reads complete

    // ---------- fill diagonal band into smem (overlay on QT/KT/VS) ----------
    float* BAND = sm;   // [64][132]
    if (P) {
        for (int t = tid; t < 64 * 33; t += NTH) {
            int r  = t / 33;
            int i4 = t - r * 33;
            int A  = (q0 + r - 127) & ~3;   // aligned base col (can be <0)
            int col = A + 4 * i4;
            const float* Prow = P + (rowbase + r) * (size_t)PS;
            float4 v;
            if (col >= 0 && col + 3 < PS) {
                v = *(const float4*)(Prow + col);
            } else {
                v.x = (col + 0 >= 0 && col + 0 < PS) ? Prow[col + 0] : 0.f;
                v.y = (col + 1 >= 0 && col + 1 < PS) ? Prow[col + 1] : 0.f;
                v.z = (col + 2 >= 0 && col + 2 < PS) ? Prow[col + 2] : 0.f;
                v.w = (col + 3 >= 0 && col + 3 < PS) ? Prow[col + 3] : 0.f;
            }
            *(float4*)(BAND + r * 132 + 4 * i4) = v;
        }
    }
    __syncthreads();

    // ---------- epilogue: rel-V via softmax identity (band from smem) ----------
    if (P) {
        float rel[4][8];
        #pragma unroll
        for (int rr = 0; rr < 4; rr++)
            #pragma unroll
            for (int cc = 0; cc < 8; cc++) rel[rr][cc] = 0.0f;

        const float* bptr[4];
        #pragma unroll
        for (int rr = 0; rr < 4; rr++) {
            int r = ty4 + rr;
            int off0 = (q0 + r - 127) & 3;
            bptr[rr] = BAND + r * 132 + off0;   // index j-1 for j=1..128
        }

        const float4* Tg = (const float4*)g_table;
        float4 ta0 = Tg[2 * tx], tb0 = Tg[2 * tx + 1];
        for (int j = 1; j <= 128; j++) {
            float4 tja = Tg[j * 16 + 2 * tx];
            float4 tjb = Tg[j * 16 + 2 * tx + 1];
            float d0 = tja.x - ta0.x, d1 = tja.y - ta0.y;
            float d2 = tja.z - ta0.z, d3 = tja.w - ta0.w;
            float d4 = tjb.x - tb0.x, d5 = tjb.y - tb0.y;
            float d6 = tjb.z - tb0.z, d7 = tjb.w - tb0.w;
            #pragma unroll
            for (int rr = 0; rr < 4; rr++) {
                float pv = bptr[rr][j - 1];
                rel[rr][0] += pv * d0; rel[rr][1] += pv * d1;
                rel[rr][2] += pv * d2; rel[rr][3] += pv * d3;
                rel[rr][4] += pv * d4; rel[rr][5] += pv * d5;
                rel[rr][6] += pv * d6; rel[rr][7] += pv * d7;
            }
        }
        #pragma unroll
        for (int rr = 0; rr < 4; rr++) {
            float o[8];
            #pragma unroll
            for (int cp = 0; cp < 4; cp++) {
                float2 t = up2(O2[rr][cp]);
                o[2 * cp] = t.x; o[2 * cp + 1] = t.y;
            }
            float li = linv[rr];
            float* orow = out + (rowbase + ty4 + rr) * PD + tx8;
            float4 r0, r1;
            r0.x = (o[0] + rel[rr][0]) * li + ta0.x;
            r0.y = (o[1] + rel[rr][1]) * li + ta0.y;
            r0.z = (o[2] + rel[rr][2]) * li + ta0.z;
            r0.w = (o[3] + rel[rr][3]) * li + ta0.w;
            r1.x = (o[4] + rel[rr][4]) * li + tb0.x;
            r1.y = (o[5] + rel[rr][5]) * li + tb0.y;
            r1.z = (o[6] + rel[rr][6]) * li + tb0.z;
            r1.w = (o[7] + rel[rr][7]) * li + tb0.w;
            *(float4*)orow       = r0;
            *(float4*)(orow + 4) = r1;
        }
    }

    // ---------- normalize P rows; zero-fill never-written region ----------
    if (P) {
        const int nt4 = nkt * 16;
        for (int idx = tid; idx < 64 * (PS / 4); idx += NTH) {
            int row = idx >> 9;
            int c4  = idx & 511;
            float4* pp = (float4*)(P + (rowbase + row) * (size_t)PS) + c4;
            if (c4 < nt4) {
                float s = LR[row];
                float4 v = *pp;
                v.x *= s; v.y *= s; v.z *= s; v.w *= s;
                *pp = v;
            } else {
                *pp = make_float4(0.f, 0.f, 0.f, 0.f);
            }
        }
    }
}

extern "C" void kernel_launch(void* const* d_in, const int* in_sizes, int n_in,
                              void* d_out, int out_size) {
    const float* Q = (const float*)d_in[0];
    const float* K = (const float*)d_in[1];
    const float* V = (const float*)d_in[2];

    float* out = (float*)d_out;
    float* P = nullptr;
    if ((size_t)out_size >= (size_t)OUT_ELEMS + PATTN_ELEMS)
        P = out + OUT_ELEMS;

    init_table_kernel<<<129, 64>>>();
    {
        dim3 tg(PS / 64, PBH, 2);
        transpose_qk_kernel<<<tg, 256>>>(K, Q);
        dim3 bg(PS / 64, PBH);
        bias_kernel<<<bg, 256>>>(Q);
    }

    size_t smem_bytes = SM_TOT * sizeof(float);
    cudaFuncSetAttribute(attn_relpos_kernel,
                         cudaFuncAttributeMaxDynamicSharedMemorySize,
                         (int)smem_bytes);
    dim3 grid(PBH, NQB);
    attn_relpos_kernel<<<grid, NTH, smem_bytes>>>(V, out, P);
}

// round 12
// speedup vs baseline: 1.3744x; 1.3744x over previous
#include <cuda_runtime.h>
#include <cstdint>
#include <math.h>

// Problem constants
#define PS   2048
#define PD   64
#define PBH  32
#define TQ   64
#define TK   64
#define NQB  (PS / TQ)     // 32
#define NTH  256

#define OUT_ELEMS   (PBH * PS * PD)
#define PATTN_ELEMS ((size_t)PBH * (size_t)PS * (size_t)PS)

// 129-row sin/cos table (causal => clipped rel index in [0,128])
__device__ float g_table[129 * 64];
// K transposed per head: [bh][d][s]
__device__ float g_KT[(size_t)PBH * PD * PS];
// bias table: g_QR[bh][s][j], j in [0,128], row stride 132
__device__ float g_QR[(size_t)PBH * PS * 132];

// ---------------- f32x2 packed-FMA helpers ----------------
__device__ __forceinline__ unsigned long long pk2(float a, float b) {
    unsigned long long r;
    asm("mov.b64 %0,{%1,%2};" : "=l"(r) : "f"(a), "f"(b));
    return r;
}
__device__ __forceinline__ float2 up2(unsigned long long v) {
    float2 r;
    asm("mov.b64 {%0,%1},%2;" : "=f"(r.x), "=f"(r.y) : "l"(v));
    return r;
}
#define FMA2(d, a, b) asm("fma.rn.f32x2 %0,%1,%2,%0;" : "+l"(d) : "l"(a), "l"(b))

__device__ __forceinline__ unsigned smem_u32(const void* p) {
    return (unsigned)__cvta_generic_to_shared(p);
}
__device__ __forceinline__ void cpa16(unsigned s, const void* g) {
    asm volatile("cp.async.cg.shared.global [%0], [%1], 16;" :: "r"(s), "l"(g));
}

__global__ void init_table_kernel() {
    int j = blockIdx.x;     // 0..128
    int d = threadIdx.x;    // 0..63
    int i2 = d & ~1;
    float div = expf((float)i2 * (-logf(10000.0f) / 64.0f));
    float ang = (float)j * div;
    g_table[j * 64 + d] = (d & 1) ? cosf(ang) : sinf(ang);
}

// One-time K transpose: K[bh][s][d] -> g_KT[bh][d][s]
__global__ void __launch_bounds__(NTH, 4)
transpose_k_kernel(const float* __restrict__ K) {
    __shared__ float t[64 * 68];
    const int tid = threadIdx.x;
    const int st  = blockIdx.x;
    const int bh  = blockIdx.y;
    const float4* Kb = (const float4*)(K + ((size_t)bh * PS + st * 64) * PD);
    #pragma unroll
    for (int i = 0; i < 4; i++) {
        int idx = tid + i * NTH;
        int row = idx >> 4, d4 = idx & 15;
        ((float4*)(t + row * 68))[d4] = Kb[idx];
    }
    __syncthreads();
    #pragma unroll
    for (int i = 0; i < 4; i++) {
        int idx = tid + i * NTH;
        int d = idx >> 4, s4 = idx & 15;
        float4 v;
        v.x = t[(4 * s4 + 0) * 68 + d];
        v.y = t[(4 * s4 + 1) * 68 + d];
        v.z = t[(4 * s4 + 2) * 68 + d];
        v.w = t[(4 * s4 + 3) * 68 + d];
        *(float4*)(g_KT + ((size_t)bh * PD + d) * PS + st * 64 + 4 * s4) = v;
    }
}

// bias pre-kernel: g_QR[bh][s][j] = (Q[bh][s]/8) . T[j]
__global__ void __launch_bounds__(NTH, 4)
bias_kernel(const float* __restrict__ Q) {
    __shared__ float qs[64 * 68];
    __shared__ float tb[129 * 68];
    const int tid = threadIdx.x;
    const int st  = blockIdx.x;
    const int bh  = blockIdx.y;
    {
        const float4* Qb = (const float4*)(Q + ((size_t)bh * PS + st * 64) * PD);
        #pragma unroll
        for (int i = 0; i < 4; i++) {
            int idx = tid + i * NTH;
            int row = idx >> 4, d4 = idx & 15;
            float4 v = Qb[idx];
            v.x *= 0.125f; v.y *= 0.125f; v.z *= 0.125f; v.w *= 0.125f;
            ((float4*)(qs + row * 68))[d4] = v;
        }
        for (int idx = tid; idx < 129 * 16; idx += NTH) {
            int row = idx >> 4, d4 = idx & 15;
            ((float4*)(tb + row * 68))[d4] = ((const float4*)g_table)[idx];
        }
    }
    __syncthreads();
    float* dst = g_QR + ((size_t)bh * PS + st * 64) * 132;
    for (int t = tid; t < 64 * 129; t += NTH) {
        int r = t / 129;
        int j = t - r * 129;
        const float4* qa = (const float4*)(qs + r * 68);
        const float4* ta = (const float4*)(tb + j * 68);
        float acc = 0.0f;
        #pragma unroll
        for (int d4 = 0; d4 < 16; d4++) {
            float4 a = qa[d4], b = ta[d4];
            acc += a.x * b.x + a.y * b.y + a.z * b.z + a.w * b.w;
        }
        dst[r * 132 + j] = acc;
    }
}

// ---------------- smem layout (floats), total 16832 = 67,328 B ----------------
#define OFF_QT 0        // [64][68]  Q^T (prescaled 1/8), d-major
#define OFF_KT 4352     // [64][64]  K^T tile
#define OFF_VS 8448     // [64][64]  V tile natural
#define OFF_PT 12544    // [64][64]  e^T tile, XOR-slot swizzled
#define OFF_LR 16640    // [64]      1/l
#define OFF_LRP 16704   // [64][2]   partial row sums (col halves)
#define SM_TOT 16832
// epilogue band overlay: [64][132] at OFF_KT (4352..12800)

__global__ void __launch_bounds__(NTH, 3)
attn_relpos_kernel(const float* __restrict__ Q,
                   const float* __restrict__ V,
                   float* __restrict__ out,
                   float* __restrict__ P)
{
    extern __shared__ float sm[];
    float* QT  = sm + OFF_QT;
    float* KT  = sm + OFF_KT;
    float* VS  = sm + OFF_VS;
    float* PT  = sm + OFF_PT;
    float* LR  = sm + OFF_LR;
    float* LRP = sm + OFF_LRP;

    const int tid = threadIdx.x;
    const int bh  = blockIdx.x;
    const int qt  = (NQB - 1) - blockIdx.y;   // heavy tiles first
    const int q0  = qt * TQ;
    // warp-shape remap: warp spans 8 col-groups x 4 row-groups
    const int tx  = tid & 7;            // col group (4 cols) within half
    const int ty  = (tid >> 3) & 15;    // row group (4 rows)
    const int ch  = tid >> 7;           // column half (0: cols 0-31, 1: 32-63)
    const int cb  = ch * 32 + tx * 4;   // col base within tile
    const int ty4 = ty * 4;
    const int nkt = qt + 1;

    // ---------- Q load (prescaled 1/8) -> QT transposed ----------
    {
        const float4* Qb = (const float4*)(Q + ((size_t)bh * PS + q0) * PD);
        #pragma unroll
        for (int i = 0; i < 4; i++) {
            int idx = tid + i * NTH;
            int row = idx >> 4, d4 = idx & 15;
            float4 v = Qb[idx];
            int db = d4 * 4;
            QT[(db + 0) * 68 + row] = v.x * 0.125f;
            QT[(db + 1) * 68 + row] = v.y * 0.125f;
            QT[(db + 2) * 68 + row] = v.z * 0.125f;
            QT[(db + 3) * 68 + row] = v.w * 0.125f;
        }
    }

    // per-row far-tile factor + bias row pointers (L2-resident)
    const float* qrRow[4];
    float rf[4];
    #pragma unroll
    for (int rr = 0; rr < 4; rr++) {
        qrRow[rr] = g_QR + ((size_t)bh * PS + q0 + ty4 + rr) * 132;
        rf[rr] = __expf(qrRow[rr][0]);
    }

    unsigned long long O2[4][2];
    #pragma unroll
    for (int rr = 0; rr < 4; rr++) { O2[rr][0] = 0ull; O2[rr][1] = 0ull; }
    float lp[4] = {0.f, 0.f, 0.f, 0.f};

    const size_t rowbase = (size_t)bh * PS + q0;
    const unsigned ktA = smem_u32(KT);
    const unsigned vsA = smem_u32(VS);
    const float* KTg0 = g_KT + (size_t)bh * PD * PS;
    const float* Vg0  = V + (size_t)bh * PS * PD;
    const int ptSlot = 4 * (ty ^ tx);   // e^T store slot (swizzled)

    for (int kt = 0; kt < nkt; kt++) {
        __syncthreads();   // prior GEMMs done with KT/VS
        // async-load K^T tile (group 0), then V tile (group 1)
        {
            const float* KTg = KTg0 + kt * TK;
            #pragma unroll
            for (int i = 0; i < 4; i++) {
                int idx = tid + i * NTH;
                int a = idx >> 4, b4 = idx & 15;
                cpa16(ktA + (a * 64 + b4 * 4) * 4, KTg + (size_t)a * PS + b4 * 4);
            }
            asm volatile("cp.async.commit_group;");
            const float* Vg = Vg0 + (size_t)kt * TK * PD;
            #pragma unroll
            for (int i = 0; i < 4; i++) {
                int idx = tid + i * NTH;
                int a = idx >> 4, b4 = idx & 15;
                cpa16(vsA + (a * 64 + b4 * 4) * 4, Vg + idx * 4);
            }
            asm volatile("cp.async.commit_group;");
        }
        asm volatile("cp.async.wait_group 1;");   // KT ready; VS may be in flight
        __syncthreads();

        // -------- QK GEMM --------
        unsigned long long acc[4][2];
        #pragma unroll
        for (int rr = 0; rr < 4; rr++) { acc[rr][0] = 0ull; acc[rr][1] = 0ull; }

        #pragma unroll 16
        for (int d = 0; d < 64; d++) {
            float4 qv = *(const float4*)(QT + d * 68 + ty4);
            ulonglong2 kp = *(const ulonglong2*)(KT + d * 64 + cb);
            unsigned long long qd0 = pk2(qv.x, qv.x), qd1 = pk2(qv.y, qv.y);
            unsigned long long qd2 = pk2(qv.z, qv.z), qd3 = pk2(qv.w, qv.w);
            FMA2(acc[0][0], qd0, kp.x); FMA2(acc[0][1], qd0, kp.y);
            FMA2(acc[1][0], qd1, kp.x); FMA2(acc[1][1], qd1, kp.y);
            FMA2(acc[2][0], qd2, kp.x); FMA2(acc[2][1], qd2, kp.y);
            FMA2(acc[3][0], qd3, kp.x); FMA2(acc[3][1], qd3, kp.y);
        }

        // -------- scores -> e --------
        float er[4][4];
        #pragma unroll
        for (int rr = 0; rr < 4; rr++) {
            float2 a = up2(acc[rr][0]), b = up2(acc[rr][1]);
            er[rr][0] = a.x; er[rr][1] = a.y; er[rr][2] = b.x; er[rr][3] = b.y;
        }

        if (kt * TK + 191 <= q0) {
            #pragma unroll
            for (int rr = 0; rr < 4; rr++)
                #pragma unroll
                for (int cc = 0; cc < 4; cc++)
                    er[rr][cc] = rf[rr] * __expf(er[rr][cc]);
        } else {
            #pragma unroll
            for (int rr = 0; rr < 4; rr++) {
                int R = ty4 + rr;
                int jbase = kt * TK + cb - (q0 + R) + 128;
                #pragma unroll
                for (int cc = 0; cc < 4; cc++) {
                    int jr = jbase + cc;
                    float ev = 0.0f;
                    if (jr <= 128) {
                        int jc = jr < 0 ? 0 : jr;
                        ev = __expf(er[rr][cc] + qrRow[rr][jc]);
                    }
                    er[rr][cc] = ev;
                }
            }
        }
        #pragma unroll
        for (int rr = 0; rr < 4; rr++)
            lp[rr] += (er[rr][0] + er[rr][1]) + (er[rr][2] + er[rr][3]);

        // unnormalized e -> global P
        if (P) {
            #pragma unroll
            for (int rr = 0; rr < 4; rr++) {
                *(float4*)(P + (rowbase + ty4 + rr) * (size_t)PS + kt * TK + cb) =
                    make_float4(er[rr][0], er[rr][1], er[rr][2], er[rr][3]);
            }
        }
        // e transposed into PT (conflict-free swizzled slots)
        #pragma unroll
        for (int cc = 0; cc < 4; cc++) {
            *(float4*)(PT + (cb + cc) * 64 + ptSlot) =
                make_float4(er[0][cc], er[1][cc], er[2][cc], er[3][cc]);
        }
        asm volatile("cp.async.wait_group 0;");   // VS ready
        __syncthreads();

        // -------- PV GEMM (swizzle constant per 4-col group) --------
        #pragma unroll 4
        for (int c4 = 0; c4 < 16; c4++) {
            const int sw = 4 * (ty ^ (c4 & 7));
            #pragma unroll
            for (int ci = 0; ci < 4; ci++) {
                int c = 4 * c4 + ci;
                float4 pv = *(const float4*)(PT + c * 64 + sw);
                ulonglong2 vp = *(const ulonglong2*)(VS + c * 64 + cb);
                unsigned long long pd0 = pk2(pv.x, pv.x), pd1 = pk2(pv.y, pv.y);
                unsigned long long pd2 = pk2(pv.z, pv.z), pd3 = pk2(pv.w, pv.w);
                FMA2(O2[0][0], pd0, vp.x); FMA2(O2[0][1], pd0, vp.y);
                FMA2(O2[1][0], pd1, vp.x); FMA2(O2[1][1], pd1, vp.y);
                FMA2(O2[2][0], pd2, vp.x); FMA2(O2[2][1], pd2, vp.y);
                FMA2(O2[3][0], pd3, vp.x); FMA2(O2[3][1], pd3, vp.y);
            }
        }
    }

    // ---------- row sums: reduce over 8 tx lanes, combine col halves ----------
    #pragma unroll
    for (int off = 1; off < 8; off <<= 1)
        #pragma unroll
        for (int rr = 0; rr < 4; rr++)
            lp[rr] += __shfl_xor_sync(0xffffffffu, lp[rr], off, 8);
    if (tx == 0) {
        #pragma unroll
        for (int rr = 0; rr < 4; rr++) LRP[(ty4 + rr) * 2 + ch] = lp[rr];
    }
    __syncthreads();
    float linv[4];
    #pragma unroll
    for (int rr = 0; rr < 4; rr++)
        linv[rr] = 1.0f / (LRP[(ty4 + rr) * 2] + LRP[(ty4 + rr) * 2 + 1]);
    if (tx == 0 && ch == 0) {
        #pragma unroll
        for (int rr = 0; rr < 4; rr++) LR[ty4 + rr] = linv[rr];
    }

    // ---------- fill diagonal band into smem (overlay on KT/VS/PT) ----------
    float* BAND = sm + OFF_KT;   // [64][132]
    if (P) {
        for (int t = tid; t < 64 * 33; t += NTH) {
            int r  = t / 33;
            int i4 = t - r * 33;
            int A  = (q0 + r - 127) & ~3;   // aligned base col (can be <0)
            int col = A + 4 * i4;
            const float* Prow = P + (rowbase + r) * (size_t)PS;
            float4 v;
            if (col >= 0 && col + 3 < PS) {
                v = *(const float4*)(Prow + col);
            } else {
                v.x = (col + 0 >= 0 && col + 0 < PS) ? Prow[col + 0] : 0.f;
                v.y = (col + 1 >= 0 && col + 1 < PS) ? Prow[col + 1] : 0.f;
                v.z = (col + 2 >= 0 && col + 2 < PS) ? Prow[col + 2] : 0.f;
                v.w = (col + 3 >= 0 && col + 3 < PS) ? Prow[col + 3] : 0.f;
            }
            *(float4*)(BAND + r * 132 + 4 * i4) = v;
        }
    }
    __syncthreads();

    // ---------- epilogue: rel-V via softmax identity (band from smem) ----------
    if (P) {
        float rel[4][4];
        #pragma unroll
        for (int rr = 0; rr < 4; rr++)
            #pragma unroll
            for (int cc = 0; cc < 4; cc++) rel[rr][cc] = 0.0f;

        const float* bptr[4];
        #pragma unroll
        for (int rr = 0; rr < 4; rr++) {
            int r = ty4 + rr;
            int off0 = (q0 + r - 127) & 3;
            bptr[rr] = BAND + r * 132 + off0;   // index j-1 for j=1..128
        }

        const float4* Tg = (const float4*)g_table;
        float4 tb0 = Tg[ch * 8 + tx];
        for (int j = 1; j <= 128; j++) {
            float4 tj = Tg[j * 16 + ch * 8 + tx];
            float dx = tj.x - tb0.x, dy = tj.y - tb0.y;
            float dz = tj.z - tb0.z, dw = tj.w - tb0.w;
            #pragma unroll
            for (int rr = 0; rr < 4; rr++) {
                float pv = bptr[rr][j - 1];
                rel[rr][0] += pv * dx;
                rel[rr][1] += pv * dy;
                rel[rr][2] += pv * dz;
                rel[rr][3] += pv * dw;
            }
        }
        #pragma unroll
        for (int rr = 0; rr < 4; rr++) {
            float2 a = up2(O2[rr][0]), b = up2(O2[rr][1]);
            float4 res;
            res.x = (a.x + rel[rr][0]) * linv[rr] + tb0.x;
            res.y = (a.y + rel[rr][1]) * linv[rr] + tb0.y;
            res.z = (b.x + rel[rr][2]) * linv[rr] + tb0.z;
            res.w = (b.y + rel[rr][3]) * linv[rr] + tb0.w;
            *(float4*)(out + (rowbase + ty4 + rr) * PD + cb) = res;
        }
    }

    // ---------- normalize P rows; zero-fill never-written region ----------
    if (P) {
        const int nt4 = nkt * 16;
        for (int idx = tid; idx < 64 * (PS / 4); idx += NTH) {
            int row = idx >> 9;
            int c4  = idx & 511;
            float4* pp = (float4*)(P + (rowbase + row) * (size_t)PS) + c4;
            if (c4 < nt4) {
                float s = LR[row];
                float4 v = *pp;
                v.x *= s; v.y *= s; v.z *= s; v.w *= s;
                *pp = v;
            } else {
                *pp = make_float4(0.f, 0.f, 0.f, 0.f);
            }
        }
    }
}

extern "C" void kernel_launch(void* const* d_in, const int* in_sizes, int n_in,
                              void* d_out, int out_size) {
    const float* Q = (const float*)d_in[0];
    const float* K = (const float*)d_in[1];
    const float* V = (const float*)d_in[2];

    float* out = (float*)d_out;
    float* P = nullptr;
    if ((size_t)out_size >= (size_t)OUT_ELEMS + PATTN_ELEMS)
        P = out + OUT_ELEMS;

    init_table_kernel<<<129, 64>>>();
    {
        dim3 tg(PS / 64, PBH);
        transpose_k_kernel<<<tg, NTH>>>(K);
        bias_kernel<<<tg, NTH>>>(Q);
    }

    size_t smem_bytes = SM_TOT * sizeof(float);
    cudaFuncSetAttribute(attn_relpos_kernel,
                         cudaFuncAttributeMaxDynamicSharedMemorySize,
                         (int)smem_bytes);
    dim3 grid(PBH, NQB);
    attn_relpos_kernel<<<grid, NTH, smem_bytes>>>(Q, V, out, P);
}

// round 16
// speedup vs baseline: 1.5273x; 1.1113x over previous
#include <cuda_runtime.h>
#include <cuda_bf16.h>
#include <mma.h>
#include <cstdint>
#include <math.h>

using namespace nvcuda;

// Problem constants
#define PS   2048
#define PD   64
#define PBH  32
#define TQ   64
#define TK   64
#define NQB  (PS / TQ)     // 32
#define NTH  256

#define OUT_ELEMS   (PBH * PS * PD)
#define PATTN_ELEMS ((size_t)PBH * (size_t)PS * (size_t)PS)

// ---------------- global scratch ----------------
__device__ float g_table[129 * 64];
// bias table: g_QR[bh][s][j], j in [0,128], row stride 132
__device__ float g_QR[(size_t)PBH * PS * 132];
// bf16 hi/lo split operands, row-major [bh][s][d] (Q prescaled by 1/8)
__device__ __nv_bfloat16 g_Qhi[(size_t)PBH * PS * PD];
__device__ __nv_bfloat16 g_Qlo[(size_t)PBH * PS * PD];
__device__ __nv_bfloat16 g_Khi[(size_t)PBH * PS * PD];
__device__ __nv_bfloat16 g_Klo[(size_t)PBH * PS * PD];

// ---------------- f32x2 packed-FMA helpers ----------------
__device__ __forceinline__ unsigned long long pk2(float a, float b) {
    unsigned long long r;
    asm("mov.b64 %0,{%1,%2};" : "=l"(r) : "f"(a), "f"(b));
    return r;
}
__device__ __forceinline__ float2 up2(unsigned long long v) {
    float2 r;
    asm("mov.b64 {%0,%1},%2;" : "=f"(r.x), "=f"(r.y) : "l"(v));
    return r;
}
#define FMA2(d, a, b) asm("fma.rn.f32x2 %0,%1,%2,%0;" : "+l"(d) : "l"(a), "l"(b))

__device__ __forceinline__ unsigned smem_u32(const void* p) {
    return (unsigned)__cvta_generic_to_shared(p);
}
__device__ __forceinline__ void cpa16(unsigned s, const void* g) {
    asm volatile("cp.async.cg.shared.global [%0], [%1], 16;" :: "r"(s), "l"(g));
}

// ---------------- pre-kernels ----------------
__global__ void init_table_kernel() {
    int j = blockIdx.x;     // 0..128
    int d = threadIdx.x;    // 0..63
    int i2 = d & ~1;
    float div = expf((float)i2 * (-logf(10000.0f) / 64.0f));
    float ang = (float)j * div;
    g_table[j * 64 + d] = (d & 1) ? cosf(ang) : sinf(ang);
}

__global__ void __launch_bounds__(256, 4)
bias_kernel(const float* __restrict__ Q) {
    __shared__ float qs[64 * 68];
    __shared__ float tb[129 * 68];
    const int tid = threadIdx.x;
    const int st  = blockIdx.x;
    const int bh  = blockIdx.y;
    {
        const float4* Qb = (const float4*)(Q + ((size_t)bh * PS + st * 64) * PD);
        #pragma unroll
        for (int i = 0; i < 4; i++) {
            int idx = tid + i * 256;
            int row = idx >> 4, d4 = idx & 15;
            float4 v = Qb[idx];
            v.x *= 0.125f; v.y *= 0.125f; v.z *= 0.125f; v.w *= 0.125f;
            ((float4*)(qs + row * 68))[d4] = v;
        }
        for (int idx = tid; idx < 129 * 16; idx += 256) {
            int row = idx >> 4, d4 = idx & 15;
            ((float4*)(tb + row * 68))[d4] = ((const float4*)g_table)[idx];
        }
    }
    __syncthreads();
    float* dst = g_QR + ((size_t)bh * PS + st * 64) * 132;
    for (int t = tid; t < 64 * 129; t += 256) {
        int r = t / 129;
        int j = t - r * 129;
        const float4* qa = (const float4*)(qs + r * 68);
        const float4* ta = (const float4*)(tb + j * 68);
        float acc = 0.0f;
        #pragma unroll
        for (int d4 = 0; d4 < 16; d4++) {
            float4 a = qa[d4], b = ta[d4];
            acc += a.x * b.x + a.y * b.y + a.z * b.z + a.w * b.w;
        }
        dst[r * 132 + j] = acc;
    }
}

// split: hi = bf16(v*scale), lo = bf16(v*scale - hi).
// Destination __device__ arrays selected IN DEVICE CODE (blockIdx.z):
// z=0 -> Q (scale 1/8), z=1 -> K (scale 1). grid(PS/64, PBH, 2)
__global__ void __launch_bounds__(256, 4)
split_qk_kernel(const float* __restrict__ Q, const float* __restrict__ K) {
    int st = blockIdx.x, bh = blockIdx.y;
    const bool isQ = (blockIdx.z == 0);
    const float* src = isQ ? Q : K;
    __nv_bfloat16* dhi = isQ ? g_Qhi : g_Khi;
    __nv_bfloat16* dlo = isQ ? g_Qlo : g_Klo;
    const float scale = isQ ? 0.125f : 1.0f;
    size_t base = ((size_t)bh * PS + st * 64) * PD;
    for (int idx = threadIdx.x; idx < 64 * PD; idx += 256) {
        float v = src[base + idx] * scale;
        __nv_bfloat16 h = __float2bfloat16(v);
        float lo = v - __bfloat162float(h);
        dhi[base + idx] = h;
        dlo[base + idx] = __float2bfloat16(lo);
    }
}

// ---------------- smem byte layout (72448 B) ----------------
#define OB_SC  0       // [64][72] f32 scores
#define OB_Q   18432   // Q hi (9216) + Q lo (9216), bf16 [64][72]
#define OB_K   36864   // K hi + K lo bf16 [64][72]; PT f32 [64][64] overlay after QK
#define OB_V   55296   // VS f32 [64][64]
#define OB_LR  71680   // 64 f32
#define OB_LRP 71936   // 128 f32
#define SM_BYTES 72448
// epilogue BAND overlay: [64][132] f32 = 33792 B at OB_K (36864..70656)

__global__ void __launch_bounds__(NTH, 3)
attn_hybrid_kernel(const float* __restrict__ V,
                   float* __restrict__ out,
                   float* __restrict__ P)
{
    extern __shared__ char smc[];
    const unsigned sb = smem_u32(smc);
    float* SC  = (float*)(smc + OB_SC);
    float* PT  = (float*)(smc + OB_K);    // overlays K after QK
    float* VS  = (float*)(smc + OB_V);
    float* LR  = (float*)(smc + OB_LR);
    float* LRP = (float*)(smc + OB_LRP);
    __nv_bfloat16* Qh_s = (__nv_bfloat16*)(smc + OB_Q);
    __nv_bfloat16* Ql_s = (__nv_bfloat16*)(smc + OB_Q + 9216);
    __nv_bfloat16* Kh_s = (__nv_bfloat16*)(smc + OB_K);
    __nv_bfloat16* Kl_s = (__nv_bfloat16*)(smc + OB_K + 9216);

    const int tid = threadIdx.x;
    const int bh  = blockIdx.x;
    const int qt  = (NQB - 1) - blockIdx.y;   // heavy tiles first
    const int q0  = qt * TQ;
    // R12 softmax/PV thread mapping
    const int tx  = tid & 7;
    const int ty  = (tid >> 3) & 15;
    const int ch  = tid >> 7;
    const int cb  = ch * 32 + tx * 4;
    const int ty4 = ty * 4;
    const int nkt = qt + 1;
    // wmma warp mapping
    const int w   = tid >> 5;
    const int m0  = (w & 3) * 16;
    const int n0  = (w >> 2) * 32;

    // ---- async-load Q hi/lo tiles (group) ----
    {
        const char* qh = (const char*)(g_Qhi + ((size_t)bh * PS + q0) * PD);
        const char* ql = (const char*)(g_Qlo + ((size_t)bh * PS + q0) * PD);
        #pragma unroll
        for (int i = 0; i < 2; i++) {
            int c = tid + i * NTH;            // 0..511
            int row = c >> 3, col = c & 7;
            cpa16(sb + OB_Q + row * 144 + col * 16, qh + c * 16);
            cpa16(sb + OB_Q + 9216 + row * 144 + col * 16, ql + c * 16);
        }
        asm volatile("cp.async.commit_group;");
    }

    // per-row far-tile factor + bias row pointers (L2-resident)
    const float* qrRow[4];
    float rf[4];
    #pragma unroll
    for (int rr = 0; rr < 4; rr++) {
        qrRow[rr] = g_QR + ((size_t)bh * PS + q0 + ty4 + rr) * 132;
        rf[rr] = __expf(qrRow[rr][0]);
    }

    unsigned long long O2[4][2];
    #pragma unroll
    for (int rr = 0; rr < 4; rr++) { O2[rr][0] = 0ull; O2[rr][1] = 0ull; }
    float lp[4] = {0.f, 0.f, 0.f, 0.f};

    const size_t rowbase = (size_t)bh * PS + q0;
    const float* Vg0 = V + (size_t)bh * PS * PD;
    const int ptSlot = 4 * (ty ^ tx);

    for (int kt = 0; kt < nkt; kt++) {
        __syncthreads();   // prior PV done with PT/VS; prior softmax done with SC
        // async-load K hi/lo (group), then V f32 (group)
        {
            const char* kh = (const char*)(g_Khi + ((size_t)bh * PS + kt * TK) * PD);
            const char* kl = (const char*)(g_Klo + ((size_t)bh * PS + kt * TK) * PD);
            #pragma unroll
            for (int i = 0; i < 2; i++) {
                int c = tid + i * NTH;
                int row = c >> 3, col = c & 7;
                cpa16(sb + OB_K + row * 144 + col * 16, kh + c * 16);
                cpa16(sb + OB_K + 9216 + row * 144 + col * 16, kl + c * 16);
            }
            asm volatile("cp.async.commit_group;");
            const float* Vg = Vg0 + (size_t)kt * TK * PD;
            #pragma unroll
            for (int i = 0; i < 4; i++) {
                int idx = tid + i * NTH;
                int a = idx >> 4, b4 = idx & 15;
                cpa16(sb + OB_V + (a * 64 + b4 * 4) * 4, Vg + idx * 4);
            }
            asm volatile("cp.async.commit_group;");
        }
        asm volatile("cp.async.wait_group 1;");   // Q + K ready; V may be in flight
        __syncthreads();

        // -------- QK^T via wmma: C = (Qh+Ql)(Kh+Kl)^T, lo*lo dropped --------
        #pragma unroll
        for (int nf = 0; nf < 2; nf++) {
            int k0 = n0 + nf * 16;
            wmma::fragment<wmma::accumulator, 16, 16, 16, float> Cf;
            wmma::fill_fragment(Cf, 0.0f);
            #pragma unroll
            for (int df = 0; df < 4; df++) {
                wmma::fragment<wmma::matrix_a, 16, 16, 16, __nv_bfloat16, wmma::row_major> Ah, Al;
                wmma::fragment<wmma::matrix_b, 16, 16, 16, __nv_bfloat16, wmma::col_major> Bh, Bl;
                wmma::load_matrix_sync(Ah, Qh_s + m0 * 72 + df * 16, 72);
                wmma::load_matrix_sync(Al, Ql_s + m0 * 72 + df * 16, 72);
                wmma::load_matrix_sync(Bh, Kh_s + k0 * 72 + df * 16, 72);
                wmma::load_matrix_sync(Bl, Kl_s + k0 * 72 + df * 16, 72);
                wmma::mma_sync(Cf, Ah, Bh, Cf);
                wmma::mma_sync(Cf, Ah, Bl, Cf);
                wmma::mma_sync(Cf, Al, Bh, Cf);
            }
            wmma::store_matrix_sync(SC + m0 * 72 + k0, Cf, 72, wmma::mem_row_major);
        }
        __syncthreads();   // SC visible; K reads done (PT overlay safe)

        // -------- scores -> e (R12 logic, scores read from SC) --------
        float er[4][4];
        #pragma unroll
        for (int rr = 0; rr < 4; rr++) {
            float4 v = *(const float4*)(SC + (ty4 + rr) * 72 + cb);
            er[rr][0] = v.x; er[rr][1] = v.y; er[rr][2] = v.z; er[rr][3] = v.w;
        }

        if (kt * TK + 191 <= q0) {
            #pragma unroll
            for (int rr = 0; rr < 4; rr++)
                #pragma unroll
                for (int cc = 0; cc < 4; cc++)
                    er[rr][cc] = rf[rr] * __expf(er[rr][cc]);
        } else {
            #pragma unroll
            for (int rr = 0; rr < 4; rr++) {
                int R = ty4 + rr;
                int jbase = kt * TK + cb - (q0 + R) + 128;
                #pragma unroll
                for (int cc = 0; cc < 4; cc++) {
                    int jr = jbase + cc;
                    float ev = 0.0f;
                    if (jr <= 128) {
                        int jc = jr < 0 ? 0 : jr;
                        ev = __expf(er[rr][cc] + qrRow[rr][jc]);
                    }
                    er[rr][cc] = ev;
                }
            }
        }
        #pragma unroll
        for (int rr = 0; rr < 4; rr++)
            lp[rr] += (er[rr][0] + er[rr][1]) + (er[rr][2] + er[rr][3]);

        // unnormalized e -> global P
        if (P) {
            #pragma unroll
            for (int rr = 0; rr < 4; rr++) {
                *(float4*)(P + (rowbase + ty4 + rr) * (size_t)PS + kt * TK + cb) =
                    make_float4(er[rr][0], er[rr][1], er[rr][2], er[rr][3]);
            }
        }
        // e transposed into PT (conflict-free swizzled slots; overlays K)
        #pragma unroll
        for (int cc = 0; cc < 4; cc++) {
            *(float4*)(PT + (cb + cc) * 64 + ptSlot) =
                make_float4(er[0][cc], er[1][cc], er[2][cc], er[3][cc]);
        }
        asm volatile("cp.async.wait_group 0;");   // VS ready
        __syncthreads();   // PT visible

        // -------- PV GEMM (FFMA2, R12 verbatim) --------
        #pragma unroll 4
        for (int c4 = 0; c4 < 16; c4++) {
            const int sw = 4 * (ty ^ (c4 & 7));
            #pragma unroll
            for (int ci = 0; ci < 4; ci++) {
                int c = 4 * c4 + ci;
                float4 pv = *(const float4*)(PT + c * 64 + sw);
                ulonglong2 vp = *(const ulonglong2*)(VS + c * 64 + cb);
                unsigned long long pd0 = pk2(pv.x, pv.x), pd1 = pk2(pv.y, pv.y);
                unsigned long long pd2 = pk2(pv.z, pv.z), pd3 = pk2(pv.w, pv.w);
                FMA2(O2[0][0], pd0, vp.x); FMA2(O2[0][1], pd0, vp.y);
                FMA2(O2[1][0], pd1, vp.x); FMA2(O2[1][1], pd1, vp.y);
                FMA2(O2[2][0], pd2, vp.x); FMA2(O2[2][1], pd2, vp.y);
                FMA2(O2[3][0], pd3, vp.x); FMA2(O2[3][1], pd3, vp.y);
            }
        }
    }

    // ---------- row sums: reduce over 8 tx lanes, combine col halves ----------
    #pragma unroll
    for (int off = 1; off < 8; off <<= 1)
        #pragma unroll
        for (int rr = 0; rr < 4; rr++)
            lp[rr] += __shfl_xor_sync(0xffffffffu, lp[rr], off, 8);
    if (tx == 0) {
        #pragma unroll
        for (int rr = 0; rr < 4; rr++) LRP[(ty4 + rr) * 2 + ch] = lp[rr];
    }
    __syncthreads();
    float linv[4];
    #pragma unroll
    for (int rr = 0; rr < 4; rr++)
        linv[rr] = 1.0f / (LRP[(ty4 + rr) * 2] + LRP[(ty4 + rr) * 2 + 1]);
    if (tx == 0 && ch == 0) {
        #pragma unroll
        for (int rr = 0; rr < 4; rr++) LR[ty4 + rr] = linv[rr];
    }

    // ---------- fill diagonal band into smem (overlay on K/PT/VS) ----------
    float* BAND = (float*)(smc + OB_K);   // [64][132]
    if (P) {
        for (int t = tid; t < 64 * 33; t += NTH) {
            int r  = t / 33;
            int i4 = t - r * 33;
            int A  = (q0 + r - 127) & ~3;   // aligned base col (can be <0)
            int col = A + 4 * i4;
            const float* Prow = P + (rowbase + r) * (size_t)PS;
            float4 v;
            if (col >= 0 && col + 3 < PS) {
                v = *(const float4*)(Prow + col);
            } else {
                v.x = (col + 0 >= 0 && col + 0 < PS) ? Prow[col + 0] : 0.f;
                v.y = (col + 1 >= 0 && col + 1 < PS) ? Prow[col + 1] : 0.f;
                v.z = (col + 2 >= 0 && col + 2 < PS) ? Prow[col + 2] : 0.f;
                v.w = (col + 3 >= 0 && col + 3 < PS) ? Prow[col + 3] : 0.f;
            }
            *(float4*)(BAND + r * 132 + 4 * i4) = v;
        }
    }
    __syncthreads();

    // ---------- epilogue: rel-V via softmax identity (band from smem) ----------
    if (P) {
        float rel[4][4];
        #pragma unroll
        for (int rr = 0; rr < 4; rr++)
            #pragma unroll
            for (int cc = 0; cc < 4; cc++) rel[rr][cc] = 0.0f;

        const float* bptr[4];
        #pragma unroll
        for (int rr = 0; rr < 4; rr++) {
            int r = ty4 + rr;
            int off0 = (q0 + r - 127) & 3;
            bptr[rr] = BAND + r * 132 + off0;   // index j-1 for j=1..128
        }

        const float4* Tg = (const float4*)g_table;
        float4 tb0 = Tg[ch * 8 + tx];
        for (int j = 1; j <= 128; j++) {
            float4 tj = Tg[j * 16 + ch * 8 + tx];
            float dx = tj.x - tb0.x, dy = tj.y - tb0.y;
            float dz = tj.z - tb0.z, dw = tj.w - tb0.w;
            #pragma unroll
            for (int rr = 0; rr < 4; rr++) {
                float pv = bptr[rr][j - 1];
                rel[rr][0] += pv * dx;
                rel[rr][1] += pv * dy;
                rel[rr][2] += pv * dz;
                rel[rr][3] += pv * dw;
            }
        }
        #pragma unroll
        for (int rr = 0; rr < 4; rr++) {
            float2 a = up2(O2[rr][0]), b = up2(O2[rr][1]);
            float4 res;
            res.x = (a.x + rel[rr][0]) * linv[rr] + tb0.x;
            res.y = (a.y + rel[rr][1]) * linv[rr] + tb0.y;
            res.z = (b.x + rel[rr][2]) * linv[rr] + tb0.z;
            res.w = (b.y + rel[rr][3]) * linv[rr] + tb0.w;
            *(float4*)(out + (rowbase + ty4 + rr) * PD + cb) = res;
        }
    }

    // ---------- normalize P rows; zero-fill never-written region ----------
    if (P) {
        const int nt4 = nkt * 16;
        for (int idx = tid; idx < 64 * (PS / 4); idx += NTH) {
            int row = idx >> 9;
            int c4  = idx & 511;
            float4* pp = (float4*)(P + (rowbase + row) * (size_t)PS) + c4;
            if (c4 < nt4) {
                float s = LR[row];
                float4 v = *pp;
                v.x *= s; v.y *= s; v.z *= s; v.w *= s;
                *pp = v;
            } else {
                *pp = make_float4(0.f, 0.f, 0.f, 0.f);
            }
        }
    }
}

extern "C" void kernel_launch(void* const* d_in, const int* in_sizes, int n_in,
                              void* d_out, int out_size) {
    const float* Q = (const float*)d_in[0];
    const float* K = (const float*)d_in[1];
    const float* V = (const float*)d_in[2];

    float* out = (float*)d_out;
    float* P = nullptr;
    if ((size_t)out_size >= (size_t)OUT_ELEMS + PATTN_ELEMS)
        P = out + OUT_ELEMS;

    init_table_kernel<<<129, 64>>>();
    {
        dim3 g(PS / 64, PBH);
        bias_kernel<<<g, 256>>>(Q);
        dim3 sg(PS / 64, PBH, 2);
        split_qk_kernel<<<sg, 256>>>(Q, K);
    }

    cudaFuncSetAttribute(attn_hybrid_kernel,
                         cudaFuncAttributeMaxDynamicSharedMemorySize, SM_BYTES);
    dim3 grid(PBH, NQB);
    attn_hybrid_kernel<<<grid, NTH, SM_BYTES>>>(V, out, P);
}

// round 17
// speedup vs baseline: 1.6595x; 1.0865x over previous
#include <cuda_runtime.h>
#include <cuda_bf16.h>
#include <mma.h>
#include <cstdint>
#include <math.h>

using namespace nvcuda;

// Problem constants
#define PS   2048
#define PD   64
#define PBH  32
#define TQ   64
#define TK   64
#define NQB  (PS / TQ)     // 32
#define NTH  256

#define OUT_ELEMS   (PBH * PS * PD)
#define PATTN_ELEMS ((size_t)PBH * (size_t)PS * (size_t)PS)

// ---------------- global scratch ----------------
__device__ float g_table[129 * 64];
// bias table: g_QR[bh][s][j], j in [0,128], row stride 132
__device__ float g_QR[(size_t)PBH * PS * 132];
// bf16 hi/lo split operands, row-major [bh][s][d] (Q prescaled by 1/8)
__device__ __nv_bfloat16 g_Qhi[(size_t)PBH * PS * PD];
__device__ __nv_bfloat16 g_Qlo[(size_t)PBH * PS * PD];
__device__ __nv_bfloat16 g_Khi[(size_t)PBH * PS * PD];
__device__ __nv_bfloat16 g_Klo[(size_t)PBH * PS * PD];
__device__ __nv_bfloat16 g_Vhi[(size_t)PBH * PS * PD];
__device__ __nv_bfloat16 g_Vlo[(size_t)PBH * PS * PD];

// ---------------- helpers ----------------
__device__ __forceinline__ unsigned smem_u32(const void* p) {
    return (unsigned)__cvta_generic_to_shared(p);
}
__device__ __forceinline__ void cpa16(unsigned s, const void* g) {
    asm volatile("cp.async.cg.shared.global [%0], [%1], 16;" :: "r"(s), "l"(g));
}

// ---------------- pre-kernels ----------------
__global__ void init_table_kernel() {
    int j = blockIdx.x;     // 0..128
    int d = threadIdx.x;    // 0..63
    int i2 = d & ~1;
    float div = expf((float)i2 * (-logf(10000.0f) / 64.0f));
    float ang = (float)j * div;
    g_table[j * 64 + d] = (d & 1) ? cosf(ang) : sinf(ang);
}

__global__ void __launch_bounds__(256, 4)
bias_kernel(const float* __restrict__ Q) {
    __shared__ float qs[64 * 68];
    __shared__ float tb[129 * 68];
    const int tid = threadIdx.x;
    const int st  = blockIdx.x;
    const int bh  = blockIdx.y;
    {
        const float4* Qb = (const float4*)(Q + ((size_t)bh * PS + st * 64) * PD);
        #pragma unroll
        for (int i = 0; i < 4; i++) {
            int idx = tid + i * 256;
            int row = idx >> 4, d4 = idx & 15;
            float4 v = Qb[idx];
            v.x *= 0.125f; v.y *= 0.125f; v.z *= 0.125f; v.w *= 0.125f;
            ((float4*)(qs + row * 68))[d4] = v;
        }
        for (int idx = tid; idx < 129 * 16; idx += 256) {
            int row = idx >> 4, d4 = idx & 15;
            ((float4*)(tb + row * 68))[d4] = ((const float4*)g_table)[idx];
        }
    }
    __syncthreads();
    float* dst = g_QR + ((size_t)bh * PS + st * 64) * 132;
    for (int t = tid; t < 64 * 129; t += 256) {
        int r = t / 129;
        int j = t - r * 129;
        const float4* qa = (const float4*)(qs + r * 68);
        const float4* ta = (const float4*)(tb + j * 68);
        float acc = 0.0f;
        #pragma unroll
        for (int d4 = 0; d4 < 16; d4++) {
            float4 a = qa[d4], b = ta[d4];
            acc += a.x * b.x + a.y * b.y + a.z * b.z + a.w * b.w;
        }
        dst[r * 132 + j] = acc;
    }
}

// split: hi = bf16(v*scale), lo = bf16(v*scale - hi).
// Destination __device__ arrays selected IN DEVICE CODE (blockIdx.z):
// z=0 -> Q (scale 1/8), z=1 -> K, z=2 -> V. grid(PS/64, PBH, 3)
__global__ void __launch_bounds__(256, 4)
split_qkv_kernel(const float* __restrict__ Q, const float* __restrict__ K,
                 const float* __restrict__ V) {
    int st = blockIdx.x, bh = blockIdx.y, z = blockIdx.z;
    const float* src = (z == 0) ? Q : (z == 1) ? K : V;
    __nv_bfloat16* dhi = (z == 0) ? g_Qhi : (z == 1) ? g_Khi : g_Vhi;
    __nv_bfloat16* dlo = (z == 0) ? g_Qlo : (z == 1) ? g_Klo : g_Vlo;
    const float scale = (z == 0) ? 0.125f : 1.0f;
    size_t base = ((size_t)bh * PS + st * 64) * PD;
    for (int idx = threadIdx.x; idx < 64 * PD; idx += 256) {
        float v = src[base + idx] * scale;
        __nv_bfloat16 h = __float2bfloat16(v);
        float lo = v - __bfloat162float(h);
        dhi[base + idx] = h;
        dlo[base + idx] = __float2bfloat16(lo);
    }
}

// ---------------- smem byte layout (74496 B) ----------------
#define OB_SC  0       // [64][72] f32 scores; O overlay at end
#define OB_Q   18432   // Q hi (9216) + Q lo (9216), bf16 [64][72]
#define OB_K   36864   // K hi + K lo bf16 [64][72]; E hi/lo overlay after QK
#define OB_V   55296   // V hi + V lo bf16 [64][72]
#define OB_LR  73728   // 64 f32
#define OB_LRP 73984   // 128 f32
#define SM_BYTES 74496
// epilogue BAND overlay: [64][132] f32 = 33792 B at OB_K (36864..70656)

__global__ void __launch_bounds__(NTH, 3)
attn_wmma2_kernel(float* __restrict__ out, float* __restrict__ P)
{
    extern __shared__ char smc[];
    const unsigned sb = smem_u32(smc);
    float* SC  = (float*)(smc + OB_SC);
    float* LR  = (float*)(smc + OB_LR);
    float* LRP = (float*)(smc + OB_LRP);
    __nv_bfloat16* Qh_s = (__nv_bfloat16*)(smc + OB_Q);
    __nv_bfloat16* Ql_s = (__nv_bfloat16*)(smc + OB_Q + 9216);
    __nv_bfloat16* Kh_s = (__nv_bfloat16*)(smc + OB_K);
    __nv_bfloat16* Kl_s = (__nv_bfloat16*)(smc + OB_K + 9216);
    __nv_bfloat16* Eh_s = Kh_s;   // overlay after QK
    __nv_bfloat16* El_s = Kl_s;
    __nv_bfloat16* Vh_s = (__nv_bfloat16*)(smc + OB_V);
    __nv_bfloat16* Vl_s = (__nv_bfloat16*)(smc + OB_V + 9216);

    const int tid = threadIdx.x;
    const int bh  = blockIdx.x;
    const int qt  = (NQB - 1) - blockIdx.y;   // heavy tiles first
    const int q0  = qt * TQ;
    // softmax thread mapping: 4 rows x 4 cols per thread
    const int tx  = tid & 7;
    const int ty  = (tid >> 3) & 15;
    const int ch  = tid >> 7;
    const int cb  = ch * 32 + tx * 4;
    const int ty4 = ty * 4;
    const int nkt = qt + 1;
    // wmma warp mapping
    const int w   = tid >> 5;
    const int m0  = (w & 3) * 16;
    const int n0  = (w >> 2) * 32;

    // ---- async-load Q hi/lo tiles (group) ----
    {
        const char* qh = (const char*)(g_Qhi + ((size_t)bh * PS + q0) * PD);
        const char* ql = (const char*)(g_Qlo + ((size_t)bh * PS + q0) * PD);
        #pragma unroll
        for (int i = 0; i < 2; i++) {
            int c = tid + i * NTH;            // 0..511
            int row = c >> 3, col = c & 7;
            cpa16(sb + OB_Q + row * 144 + col * 16, qh + c * 16);
            cpa16(sb + OB_Q + 9216 + row * 144 + col * 16, ql + c * 16);
        }
        asm volatile("cp.async.commit_group;");
    }

    // per-row far-tile factor + bias row pointers (L2-resident)
    const float* qrRow[4];
    float rf[4];
    #pragma unroll
    for (int rr = 0; rr < 4; rr++) {
        qrRow[rr] = g_QR + ((size_t)bh * PS + q0 + ty4 + rr) * 132;
        rf[rr] = __expf(qrRow[rr][0]);
    }

    // O accumulators (wmma, per warp)
    wmma::fragment<wmma::accumulator, 16, 16, 16, float> Of[2];
    wmma::fill_fragment(Of[0], 0.0f);
    wmma::fill_fragment(Of[1], 0.0f);
    float lp[4] = {0.f, 0.f, 0.f, 0.f};

    const size_t rowbase = (size_t)bh * PS + q0;

    for (int kt = 0; kt < nkt; kt++) {
        __syncthreads();   // prior PV done with E/V; prior softmax done with SC
        // async-load K hi/lo (group), then V hi/lo (group)
        {
            const char* kh = (const char*)(g_Khi + ((size_t)bh * PS + kt * TK) * PD);
            const char* kl = (const char*)(g_Klo + ((size_t)bh * PS + kt * TK) * PD);
            #pragma unroll
            for (int i = 0; i < 2; i++) {
                int c = tid + i * NTH;
                int row = c >> 3, col = c & 7;
                cpa16(sb + OB_K + row * 144 + col * 16, kh + c * 16);
                cpa16(sb + OB_K + 9216 + row * 144 + col * 16, kl + c * 16);
            }
            asm volatile("cp.async.commit_group;");
            const char* vh = (const char*)(g_Vhi + ((size_t)bh * PS + kt * TK) * PD);
            const char* vl = (const char*)(g_Vlo + ((size_t)bh * PS + kt * TK) * PD);
            #pragma unroll
            for (int i = 0; i < 2; i++) {
                int c = tid + i * NTH;
                int row = c >> 3, col = c & 7;
                cpa16(sb + OB_V + row * 144 + col * 16, vh + c * 16);
                cpa16(sb + OB_V + 9216 + row * 144 + col * 16, vl + c * 16);
            }
            asm volatile("cp.async.commit_group;");
        }
        asm volatile("cp.async.wait_group 1;");   // Q + K ready; V may be in flight
        __syncthreads();

        // -------- QK^T via wmma: C = (Qh+Ql)(Kh+Kl)^T, lo*lo dropped --------
        #pragma unroll
        for (int nf = 0; nf < 2; nf++) {
            int k0 = n0 + nf * 16;
            wmma::fragment<wmma::accumulator, 16, 16, 16, float> Cf;
            wmma::fill_fragment(Cf, 0.0f);
            #pragma unroll
            for (int df = 0; df < 4; df++) {
                wmma::fragment<wmma::matrix_a, 16, 16, 16, __nv_bfloat16, wmma::row_major> Ah, Al;
                wmma::fragment<wmma::matrix_b, 16, 16, 16, __nv_bfloat16, wmma::col_major> Bh, Bl;
                wmma::load_matrix_sync(Ah, Qh_s + m0 * 72 + df * 16, 72);
                wmma::load_matrix_sync(Al, Ql_s + m0 * 72 + df * 16, 72);
                wmma::load_matrix_sync(Bh, Kh_s + k0 * 72 + df * 16, 72);
                wmma::load_matrix_sync(Bl, Kl_s + k0 * 72 + df * 16, 72);
                wmma::mma_sync(Cf, Ah, Bh, Cf);
                wmma::mma_sync(Cf, Ah, Bl, Cf);
                wmma::mma_sync(Cf, Al, Bh, Cf);
            }
            wmma::store_matrix_sync(SC + m0 * 72 + k0, Cf, 72, wmma::mem_row_major);
        }
        __syncthreads();   // SC visible; K reads done (E overlay safe)

        // -------- scores -> e --------
        float er[4][4];
        #pragma unroll
        for (int rr = 0; rr < 4; rr++) {
            float4 v = *(const float4*)(SC + (ty4 + rr) * 72 + cb);
            er[rr][0] = v.x; er[rr][1] = v.y; er[rr][2] = v.z; er[rr][3] = v.w;
        }

        if (kt * TK + 191 <= q0) {
            #pragma unroll
            for (int rr = 0; rr < 4; rr++)
                #pragma unroll
                for (int cc = 0; cc < 4; cc++)
                    er[rr][cc] = rf[rr] * __expf(er[rr][cc]);
        } else {
            #pragma unroll
            for (int rr = 0; rr < 4; rr++) {
                int R = ty4 + rr;
                int jbase = kt * TK + cb - (q0 + R) + 128;
                #pragma unroll
                for (int cc = 0; cc < 4; cc++) {
                    int jr = jbase + cc;
                    float ev = 0.0f;
                    if (jr <= 128) {
                        int jc = jr < 0 ? 0 : jr;
                        ev = __expf(er[rr][cc] + qrRow[rr][jc]);
                    }
                    er[rr][cc] = ev;
                }
            }
        }
        #pragma unroll
        for (int rr = 0; rr < 4; rr++)
            lp[rr] += (er[rr][0] + er[rr][1]) + (er[rr][2] + er[rr][3]);

        // unnormalized e -> global P
        if (P) {
            #pragma unroll
            for (int rr = 0; rr < 4; rr++) {
                *(float4*)(P + (rowbase + ty4 + rr) * (size_t)PS + kt * TK + cb) =
                    make_float4(er[rr][0], er[rr][1], er[rr][2], er[rr][3]);
            }
        }
        // e -> bf16 hi/lo into E tiles (row-major, overlays K)
        #pragma unroll
        for (int rr = 0; rr < 4; rr++) {
            __nv_bfloat16 h0 = __float2bfloat16(er[rr][0]);
            __nv_bfloat16 h1 = __float2bfloat16(er[rr][1]);
            __nv_bfloat16 h2 = __float2bfloat16(er[rr][2]);
            __nv_bfloat16 h3 = __float2bfloat16(er[rr][3]);
            __nv_bfloat162 hp0; hp0.x = h0; hp0.y = h1;
            __nv_bfloat162 hp1; hp1.x = h2; hp1.y = h3;
            __nv_bfloat162 lq0, lq1;
            lq0.x = __float2bfloat16(er[rr][0] - __bfloat162float(h0));
            lq0.y = __float2bfloat16(er[rr][1] - __bfloat162float(h1));
            lq1.x = __float2bfloat16(er[rr][2] - __bfloat162float(h2));
            lq1.y = __float2bfloat16(er[rr][3] - __bfloat162float(h3));
            unsigned off = (ty4 + rr) * 144 + cb * 2;
            *(uint2*)(smc + OB_K + off) =
                make_uint2(*(uint32_t*)&hp0, *(uint32_t*)&hp1);
            *(uint2*)(smc + OB_K + 9216 + off) =
                make_uint2(*(uint32_t*)&lq0, *(uint32_t*)&lq1);
        }
        asm volatile("cp.async.wait_group 0;");   // V ready
        __syncthreads();   // E visible

        // -------- PV via wmma: O += (Eh+El)(Vh+Vl), lo*lo dropped --------
        #pragma unroll
        for (int nf = 0; nf < 2; nf++) {
            int dcol = n0 + nf * 16;
            #pragma unroll
            for (int kf = 0; kf < 4; kf++) {
                wmma::fragment<wmma::matrix_a, 16, 16, 16, __nv_bfloat16, wmma::row_major> Eh, El;
                wmma::fragment<wmma::matrix_b, 16, 16, 16, __nv_bfloat16, wmma::row_major> Vh, Vl;
                wmma::load_matrix_sync(Eh, Eh_s + m0 * 72 + kf * 16, 72);
                wmma::load_matrix_sync(El, El_s + m0 * 72 + kf * 16, 72);
                wmma::load_matrix_sync(Vh, Vh_s + (kf * 16) * 72 + dcol, 72);
                wmma::load_matrix_sync(Vl, Vl_s + (kf * 16) * 72 + dcol, 72);
                wmma::mma_sync(Of[nf], Eh, Vh, Of[nf]);
                wmma::mma_sync(Of[nf], Eh, Vl, Of[nf]);
                wmma::mma_sync(Of[nf], El, Vh, Of[nf]);
            }
        }
    }
    __syncthreads();   // mainloop done; SC free for O

    // ---- store O to SC overlay ----
    wmma::store_matrix_sync(SC + m0 * 72 + n0,      Of[0], 72, wmma::mem_row_major);
    wmma::store_matrix_sync(SC + m0 * 72 + n0 + 16, Of[1], 72, wmma::mem_row_major);

    // ---------- row sums: reduce over 8 tx lanes, combine col halves ----------
    #pragma unroll
    for (int off = 1; off < 8; off <<= 1)
        #pragma unroll
        for (int rr = 0; rr < 4; rr++)
            lp[rr] += __shfl_xor_sync(0xffffffffu, lp[rr], off, 8);
    if (tx == 0) {
        #pragma unroll
        for (int rr = 0; rr < 4; rr++) LRP[(ty4 + rr) * 2 + ch] = lp[rr];
    }
    __syncthreads();
    float linv[4];
    #pragma unroll
    for (int rr = 0; rr < 4; rr++)
        linv[rr] = 1.0f / (LRP[(ty4 + rr) * 2] + LRP[(ty4 + rr) * 2 + 1]);
    if (tx == 0 && ch == 0) {
        #pragma unroll
        for (int rr = 0; rr < 4; rr++) LR[ty4 + rr] = linv[rr];
    }

    // ---------- fill diagonal band into smem (overlay on E/V regions) ----------
    float* BAND = (float*)(smc + OB_K);   // [64][132]
    if (P) {
        for (int t = tid; t < 64 * 33; t += NTH) {
            int r  = t / 33;
            int i4 = t - r * 33;
            int A  = (q0 + r - 127) & ~3;   // aligned base col (can be <0)
            int col = A + 4 * i4;
            const float* Prow = P + (rowbase + r) * (size_t)PS;
            float4 v;
            if (col >= 0 && col + 3 < PS) {
                v = *(const float4*)(Prow + col);
            } else {
                v.x = (col + 0 >= 0 && col + 0 < PS) ? Prow[col + 0] : 0.f;
                v.y = (col + 1 >= 0 && col + 1 < PS) ? Prow[col + 1] : 0.f;
                v.z = (col + 2 >= 0 && col + 2 < PS) ? Prow[col + 2] : 0.f;
                v.w = (col + 3 >= 0 && col + 3 < PS) ? Prow[col + 3] : 0.f;
            }
            *(float4*)(BAND + r * 132 + 4 * i4) = v;
        }
    }
    __syncthreads();

    // ---------- epilogue: rel-V via softmax identity (band from smem) ----------
    if (P) {
        float rel[4][4];
        #pragma unroll
        for (int rr = 0; rr < 4; rr++)
            #pragma unroll
            for (int cc = 0; cc < 4; cc++) rel[rr][cc] = 0.0f;

        const float* bptr[4];
        #pragma unroll
        for (int rr = 0; rr < 4; rr++) {
            int r = ty4 + rr;
            int off0 = (q0 + r - 127) & 3;
            bptr[rr] = BAND + r * 132 + off0;   // index j-1 for j=1..128
        }

        const float4* Tg = (const float4*)g_table;
        float4 tb0 = Tg[ch * 8 + tx];
        for (int j = 1; j <= 128; j++) {
            float4 tj = Tg[j * 16 + ch * 8 + tx];
            float dx = tj.x - tb0.x, dy = tj.y - tb0.y;
            float dz = tj.z - tb0.z, dw = tj.w - tb0.w;
            #pragma unroll
            for (int rr = 0; rr < 4; rr++) {
                float pv = bptr[rr][j - 1];
                rel[rr][0] += pv * dx;
                rel[rr][1] += pv * dy;
                rel[rr][2] += pv * dz;
                rel[rr][3] += pv * dw;
            }
        }
        #pragma unroll
        for (int rr = 0; rr < 4; rr++) {
            const float* orow = SC + (ty4 + rr) * 72 + cb;
            float4 res;
            res.x = (orow[0] + rel[rr][0]) * linv[rr] + tb0.x;
            res.y = (orow[1] + rel[rr][1]) * linv[rr] + tb0.y;
            res.z = (orow[2] + rel[rr][2]) * linv[rr] + tb0.z;
            res.w = (orow[3] + rel[rr][3]) * linv[rr] + tb0.w;
            *(float4*)(out + (rowbase + ty4 + rr) * PD + cb) = res;
        }
    }

    // ---------- normalize P rows; zero-fill never-written region ----------
    if (P) {
        const int nt4 = nkt * 16;
        for (int idx = tid; idx < 64 * (PS / 4); idx += NTH) {
            int row = idx >> 9;
            int c4  = idx & 511;
            float4* pp = (float4*)(P + (rowbase + row) * (size_t)PS) + c4;
            if (c4 < nt4) {
                float s = LR[row];
                float4 v = *pp;
                v.x *= s; v.y *= s; v.z *= s; v.w *= s;
                *pp = v;
            } else {
                *pp = make_float4(0.f, 0.f, 0.f, 0.f);
            }
        }
    }
}

extern "C" void kernel_launch(void* const* d_in, const int* in_sizes, int n_in,
                              void* d_out, int out_size) {
    const float* Q = (const float*)d_in[0];
    const float* K = (const float*)d_in[1];
    const float* V = (const float*)d_in[2];

    float* out = (float*)d_out;
    float* P = nullptr;
    if ((size_t)out_size >= (size_t)OUT_ELEMS + PATTN_ELEMS)
        P = out + OUT_ELEMS;

    init_table_kernel<<<129, 64>>>();
    {
        dim3 g(PS / 64, PBH);
        bias_kernel<<<g, 256>>>(Q);
        dim3 sg(PS / 64, PBH, 3);
        split_qkv_kernel<<<sg, 256>>>(Q, K, V);
    }

    cudaFuncSetAttribute(attn_wmma2_kernel,
                         cudaFuncAttributeMaxDynamicSharedMemorySize, SM_BYTES);
    dim3 grid(PBH, NQB);
    attn_wmma2_kernel<<<grid, NTH, SM_BYTES>>>(out, P);
}